// round 1
// baseline (speedup 1.0000x reference)
#include <cuda_runtime.h>

#define NB   4
#define CIN  256
#define CO   128
#define HIN  64
#define HH   128

// Scratch (device globals are the sanctioned scratch mechanism: no allocs allowed)
__device__ float g_y[(size_t)NB * CO * HH * HH];   // stage-1 output, NCHW
__device__ float g_k[(size_t)NB * 9 * HH * HH];    // PAC gaussian weights, [b][tap][h][w]

// ---------------------------------------------------------------------------
// Stage 1: ConvTranspose2d(256->128, k=4, s=2, p=1), decomposed into the 4
// output-parity classes. For class (p,q), output (oh,ow)=(2a+p, 2bb+q) is a
// 2x2 conv over x with taps:
//   p=0: (kh=1, ih=a), (kh=3, ih=a-1)     p=1: (kh=0, ih=a+1), (kh=2, ih=a)
//   q=0: (kw=1, iw=bb),(kw=3, iw=bb-1)    q=1: (kw=0, iw=bb+1),(kw=2, iw=bb)
// Block: fixed (b, p, a); computes all 128 co x 64 bb. 256 threads, each
// owns a 16(co) x 2(bb) micro-tile. Q is a template so xv indices stay static.
// ---------------------------------------------------------------------------
template <int Q>
__global__ __launch_bounds__(256, 2) void stage1_kernel(
    const float* __restrict__ x, const float* __restrict__ w1,
    const float* __restrict__ b1)
{
    const int a   = blockIdx.x;          // 0..63
    const int p   = blockIdx.y;          // 0..1
    const int b   = blockIdx.z;          // 0..3
    const int tid = threadIdx.x;
    const int to  = tid >> 5;            // 0..7  -> co base = to*16
    const int tw  = tid & 31;            // 0..31 -> bb pair = 2*tw,2*tw+1

    const int khb = p ? 0 : 1;
    const int kwb = Q ? 0 : 1;
    const int r0  = a + (p ? 1 : 0);     // x row for s=0; s=1 uses r0-1
    constexpr int M0 = Q ? 2 : 1;        // xv index offset for t=0 (t=1 -> M0-1)

    __shared__ float4 wsm[8][128];       // taps packed (s,t): (0,0)(0,1)(1,0)(1,1)
    __shared__ float  xsm[8][2][66];     // [ci][s][iw+1], iw in [-1,64]

    float acc[16][2];
#pragma unroll
    for (int i = 0; i < 16; i++) { acc[i][0] = 0.f; acc[i][1] = 0.f; }

    const float* xb = x + (size_t)b * CIN * HIN * HIN;

    for (int c0 = 0; c0 < CIN; c0 += 8) {
        __syncthreads();
        // weights: 8ci x 128co x 4 taps
#pragma unroll 4
        for (int i = tid; i < 8 * 128; i += 256) {
            int ci = i >> 7, co = i & 127;
            const float* wp = w1 + ((size_t)(c0 + ci) * CO + co) * 16;
            float4 v;
            v.x = __ldg(wp + khb * 4 + kwb);
            v.y = __ldg(wp + khb * 4 + kwb + 2);
            v.z = __ldg(wp + (khb + 2) * 4 + kwb);
            v.w = __ldg(wp + (khb + 2) * 4 + kwb + 2);
            wsm[ci][co] = v;
        }
        // x slab: 8ci x 2 rows x 66 cols, zero-padded
        for (int i = tid; i < 8 * 2 * 66; i += 256) {
            int ci = i / 132, r = i % 132;
            int s = r / 66, col = r % 66;
            int ih = r0 - s;
            int iw = col - 1;
            float v = 0.f;
            if ((unsigned)ih < (unsigned)HIN && (unsigned)iw < (unsigned)HIN)
                v = __ldg(xb + ((size_t)(c0 + ci) * HIN + ih) * HIN + iw);
            xsm[ci][s][col] = v;
        }
        __syncthreads();

#pragma unroll
        for (int ci = 0; ci < 8; ci++) {
            float xv0[4], xv1[4];
#pragma unroll
            for (int m = 0; m < 4; m++) {
                xv0[m] = xsm[ci][0][2 * tw + m];
                xv1[m] = xsm[ci][1][2 * tw + m];
            }
#pragma unroll
            for (int oi = 0; oi < 16; oi++) {
                float4 wv = wsm[ci][to * 16 + oi];   // uniform broadcast per warp
#pragma unroll
                for (int e = 0; e < 2; e++) {
                    float s_ = acc[oi][e];
                    s_ = fmaf(wv.x, xv0[e + M0],     s_);
                    s_ = fmaf(wv.y, xv0[e + M0 - 1], s_);
                    s_ = fmaf(wv.z, xv1[e + M0],     s_);
                    s_ = fmaf(wv.w, xv1[e + M0 - 1], s_);
                    acc[oi][e] = s_;
                }
            }
        }
    }

    const int oh = 2 * a + p;
#pragma unroll
    for (int oi = 0; oi < 16; oi++) {
        int co = to * 16 + oi;
        float bias = __ldg(b1 + co);
#pragma unroll
        for (int e = 0; e < 2; e++) {
            int ow = 4 * tw + 2 * e + Q;
            g_y[(((size_t)b * CO + co) * HH + oh) * HH + ow] = acc[oi][e] + bias;
        }
    }
}

// ---------------------------------------------------------------------------
// Stage 2a: PAC gaussian kernel map.
// k[b,tap,h,w] = exp(-0.5 * sum_c (guide[b,c,nh,nw] - guide[b,c,h,w])^2),
// neighbors zero-padded. 16x16 tile, smem 18x18 per channel slice.
// ---------------------------------------------------------------------------
__global__ __launch_bounds__(256) void kmap_kernel(const float* __restrict__ guide)
{
    const int b  = blockIdx.z;
    const int h0 = blockIdx.y * 16, w0 = blockIdx.x * 16;
    const int tx = threadIdx.x & 15, ty = threadIdx.x >> 4;

    __shared__ float sm[18][18];
    float acc[9];
#pragma unroll
    for (int t = 0; t < 9; t++) acc[t] = 0.f;

    for (int c = 0; c < CO; c++) {
        __syncthreads();
        for (int i = threadIdx.x; i < 18 * 18; i += 256) {
            int r = i / 18, col = i % 18;
            int h = h0 + r - 1, w = w0 + col - 1;
            float v = 0.f;
            if ((unsigned)h < (unsigned)HH && (unsigned)w < (unsigned)HH)
                v = __ldg(guide + (((size_t)b * CO + c) * HH + h) * HH + w);
            sm[r][col] = v;
        }
        __syncthreads();
        float g0 = sm[ty + 1][tx + 1];
#pragma unroll
        for (int i3 = 0; i3 < 3; i3++)
#pragma unroll
            for (int j3 = 0; j3 < 3; j3++) {
                float d = sm[ty + i3][tx + j3] - g0;
                acc[i3 * 3 + j3] = fmaf(d, d, acc[i3 * 3 + j3]);
            }
    }

    int h = h0 + ty, w = w0 + tx;
#pragma unroll
    for (int t = 0; t < 9; t++)
        g_k[(((size_t)b * 9 + t) * HH + h) * HH + w] = __expf(-0.5f * acc[t]);
}

// ---------------------------------------------------------------------------
// Stage 2b: out[b,o,h,w] = b2[o] + sum_{c,t} wk[o,c,t] * y[b,c,nh,nw] * k[b,t,h,w]
// with wk[o,c,t] = w2[c,o,8-t] (the 180-degree flip collapses to index 8-t).
// Block: fixed (b,h,wtile of 64); 128 o x 64 px; 256 threads, 16(o) x 2(px)
// micro-tile; k held in registers for the whole block; weights broadcast-loaded.
// ---------------------------------------------------------------------------
__global__ __launch_bounds__(256, 2) void stage2_kernel(
    const float* __restrict__ w2, const float* __restrict__ b2,
    float* __restrict__ out)
{
    const int wstart = blockIdx.x * 64;
    const int h      = blockIdx.y;
    const int b      = blockIdx.z;
    const int tid    = threadIdx.x;
    const int to     = tid >> 5;         // 0..7 -> o base = to*16
    const int tw     = tid & 31;         // px pair = wstart + 2*tw + {0,1}
    const int w      = wstart + 2 * tw;

    __shared__ __align__(16) float wsm[4][128][12];  // 9 taps + pad for float4
    __shared__ float ysm[4][3][66];

    float kreg[2][9];
#pragma unroll
    for (int t = 0; t < 9; t++) {
        kreg[0][t] = g_k[(((size_t)b * 9 + t) * HH + h) * HH + w];
        kreg[1][t] = g_k[(((size_t)b * 9 + t) * HH + h) * HH + w + 1];
    }

    float acc[16][2];
#pragma unroll
    for (int i = 0; i < 16; i++) { acc[i][0] = 0.f; acc[i][1] = 0.f; }

    for (int c0 = 0; c0 < CO; c0 += 4) {
        __syncthreads();
        // weights with flip: wsm[c][o][t] = w2[(c0+c)*128*9 + o*9 + 8 - t]
        for (int i = tid; i < 4 * 128 * 9; i += 256) {
            int c = i / 1152, r = i % 1152, o = r / 9, t = r % 9;
            wsm[c][o][t] = __ldg(w2 + ((size_t)(c0 + c) * CO + o) * 9 + 8 - t);
        }
        // y slab: 4c x 3 rows x 66 cols, zero-padded
        for (int i = tid; i < 4 * 3 * 66; i += 256) {
            int c = i / 198, r = i % 198, row = r / 66, col = r % 66;
            int hh = h + row - 1, ww = wstart + col - 1;
            float v = 0.f;
            if ((unsigned)hh < (unsigned)HH && (unsigned)ww < (unsigned)HH)
                v = g_y[(((size_t)b * CO + c0 + c) * HH + hh) * HH + ww];
            ysm[c][row][col] = v;
        }
        __syncthreads();

#pragma unroll
        for (int c = 0; c < 4; c++) {
            float z[2][9];
#pragma unroll
            for (int i3 = 0; i3 < 3; i3++) {
                float y0 = ysm[c][i3][2 * tw + 0];
                float y1 = ysm[c][i3][2 * tw + 1];
                float y2 = ysm[c][i3][2 * tw + 2];
                float y3 = ysm[c][i3][2 * tw + 3];
                z[0][i3 * 3 + 0] = y0 * kreg[0][i3 * 3 + 0];
                z[0][i3 * 3 + 1] = y1 * kreg[0][i3 * 3 + 1];
                z[0][i3 * 3 + 2] = y2 * kreg[0][i3 * 3 + 2];
                z[1][i3 * 3 + 0] = y1 * kreg[1][i3 * 3 + 0];
                z[1][i3 * 3 + 1] = y2 * kreg[1][i3 * 3 + 1];
                z[1][i3 * 3 + 2] = y3 * kreg[1][i3 * 3 + 2];
            }
#pragma unroll
            for (int oi = 0; oi < 16; oi++) {
                const float* wp = &wsm[c][to * 16 + oi][0];  // uniform per warp
                float4 wa = *(const float4*)wp;
                float4 wb = *(const float4*)(wp + 4);
                float  wc = wp[8];
#pragma unroll
                for (int e = 0; e < 2; e++) {
                    float s_ = acc[oi][e];
                    s_ = fmaf(wa.x, z[e][0], s_);
                    s_ = fmaf(wa.y, z[e][1], s_);
                    s_ = fmaf(wa.z, z[e][2], s_);
                    s_ = fmaf(wa.w, z[e][3], s_);
                    s_ = fmaf(wb.x, z[e][4], s_);
                    s_ = fmaf(wb.y, z[e][5], s_);
                    s_ = fmaf(wb.z, z[e][6], s_);
                    s_ = fmaf(wb.w, z[e][7], s_);
                    s_ = fmaf(wc,   z[e][8], s_);
                    acc[oi][e] = s_;
                }
            }
        }
    }

#pragma unroll
    for (int oi = 0; oi < 16; oi++) {
        int o = to * 16 + oi;
        float bias = __ldg(b2 + o);
        float2 v = make_float2(acc[oi][0] + bias, acc[oi][1] + bias);
        *(float2*)&out[(((size_t)b * CO + o) * HH + h) * HH + w] = v;
    }
}

// ---------------------------------------------------------------------------
extern "C" void kernel_launch(void* const* d_in, const int* in_sizes, int n_in,
                              void* d_out, int out_size)
{
    (void)in_sizes; (void)n_in; (void)out_size;
    const float* x     = (const float*)d_in[0];
    const float* guide = (const float*)d_in[1];
    const float* w1    = (const float*)d_in[2];
    const float* b1    = (const float*)d_in[3];
    const float* w2    = (const float*)d_in[4];
    const float* b2    = (const float*)d_in[5];
    float* out = (float*)d_out;

    // Stage 1: two parity-templated launches cover all 4 classes
    stage1_kernel<0><<<dim3(64, 2, NB), 256>>>(x, w1, b1);
    stage1_kernel<1><<<dim3(64, 2, NB), 256>>>(x, w1, b1);
    // Stage 2a: gaussian kernel map (independent of stage 1; same-stream order is fine)
    kmap_kernel<<<dim3(8, 8, NB), 256>>>(guide);
    // Stage 2b: PAC transposed conv
    stage2_kernel<<<dim3(2, HH, NB), 256>>>(w2, b2, out);
}